// round 16
// baseline (speedup 1.0000x reference)
#include <cuda_runtime.h>
#include <cstdint>

// Problem constants (fixed by the dataset)
#define H   1024
#define LL  4
#define BB  128
#define SS  512
#define VV  128

// Dual-copy shared layouts in recur_kernel (Round-10/12 winner):
//  comb_all: [0,2048) copy0 = [n | h]; [2048, 2048+2112) copy1 skewed (addr = 2048 + i + (i>>5))
//  t_all:    [0,1024) copy0;           [1024, 1024+1056) copy1 skewed (addr = 1024 + i + (i>>5))
#define COMB_ALL_SZ 4160
#define T_ALL_SZ    2080

// ---------------------------------------------------------------------------
// Scratch (device globals — no allocation allowed in kernel_launch)
// ---------------------------------------------------------------------------
__device__ float4   g_cn [LL*H];
__device__ float4   g_ck [LL*H];
__device__ float4   g_cm [LL*H];
__device__ float4   g_cmf[2*H];
__device__ unsigned g_in [LL*H];
__device__ unsigned g_ik [LL*H];
__device__ unsigned g_im [LL*H];
__device__ unsigned g_imf[2*H];
__device__ float    g_ntab[VV*H];      // n-branch output per token

// Fused k super-layers (written by the scheduler)
__device__ float4   g_fkc[2*H*4];      // slot-permuted multilinear coeffs
__device__ uint2    g_fka[2*H];        // physical smem addresses (4 x 16-bit)

// ---------------------------------------------------------------------------
// Kernel A: softmax(w) -> affine gate coefficients, pack gather indices.
// Gate basis: out = c0 + c1*a + c2*b + c3*a*b
// Weight rows loaded as 4 x LDG128 (16-float rows are 64B aligned).
// ---------------------------------------------------------------------------
__global__ void precompute_coef(
    const float* __restrict__ n_w, const float* __restrict__ k_w,
    const float* __restrict__ m_w, const float* __restrict__ mf_w,
    const int* __restrict__ n_idx, const int* __restrict__ k_idx0,
    const int* __restrict__ k_idx_rest, const int* __restrict__ m_idx0,
    const int* __restrict__ m_idx_rest, const int* __restrict__ m_idx_fin)
{
    int g = blockIdx.x * blockDim.x + threadIdx.x;
    const int NG = 3 * LL * H + 2 * H;   // 14336
    if (g >= NG) return;

    const float* w; int i0, i1; float4* cdst; unsigned* idst; int slot;
    if (g < LL * H) {
        int l = g >> 10, o = g & (H - 1);
        w = n_w + (l * H + o) * 16;
        i0 = n_idx[(l * 2 + 0) * H + o];
        i1 = n_idx[(l * 2 + 1) * H + o];
        cdst = g_cn; idst = g_in; slot = g;
    } else if (g < 2 * LL * H) {
        int gg = g - LL * H, l = gg >> 10, o = gg & (H - 1);
        w = k_w + (l * H + o) * 16;
        if (l == 0) { i0 = k_idx0[o]; i1 = k_idx0[H + o]; }
        else        { i0 = k_idx_rest[((l - 1) * 2 + 0) * H + o];
                      i1 = k_idx_rest[((l - 1) * 2 + 1) * H + o]; }
        cdst = g_ck; idst = g_ik; slot = gg;
    } else if (g < 3 * LL * H) {
        int gg = g - 2 * LL * H, l = gg >> 10, o = gg & (H - 1);
        w = m_w + (l * H + o) * 16;
        if (l == 0) { i0 = m_idx0[o]; i1 = m_idx0[H + o]; }
        else        { i0 = m_idx_rest[((l - 1) * 2 + 0) * H + o];
                      i1 = m_idx_rest[((l - 1) * 2 + 1) * H + o]; }
        cdst = g_cm; idst = g_im; slot = gg;
    } else {
        int j = g - 3 * LL * H;               // 0..2047
        w = mf_w + j * 16;
        i0 = m_idx_fin[j]; i1 = m_idx_fin[2 * H + j];
        cdst = g_cmf; idst = g_imf; slot = j;
    }

    const float4* w4 = reinterpret_cast<const float4*>(w);
    float4 wa = w4[0], wb = w4[1], wc = w4[2], wd = w4[3];
    float p[16] = { wa.x, wa.y, wa.z, wa.w,  wb.x, wb.y, wb.z, wb.w,
                    wc.x, wc.y, wc.z, wc.w,  wd.x, wd.y, wd.z, wd.w };

    float mx = p[0];
#pragma unroll
    for (int i = 1; i < 16; i++) mx = fmaxf(mx, p[i]);
    float s = 0.f;
#pragma unroll
    for (int i = 0; i < 16; i++) { p[i] = expf(p[i] - mx); s += p[i]; }
    float inv = 1.0f / s;
#pragma unroll
    for (int i = 0; i < 16; i++) p[i] *= inv;

    float c0 = p[8] + p[9] + p[10] + p[11] + p[12] + p[13] + p[14] + p[15];
    float c1 = p[2] + p[3] + p[6] + p[7] - p[8] - p[9] - p[12] - p[13];
    float c2 = p[4] + p[5] + p[6] + p[7] - p[8] - p[9] - p[10] - p[11];
    float c3 = p[1] - p[2] - p[4] - 2.f * p[6] - p[7]
             + p[8] + 2.f * p[9] + p[11] + p[13] - p[14];

    cdst[slot] = make_float4(c0, c1, c2, c3);
    idst[slot] = (unsigned)i0 | ((unsigned)i1 << 16);
}

// ---------------------------------------------------------------------------
// Kernel B+S merged (Round-12 exact): blocks [0,VV) compute N_table rows;
// blocks [VV,VV+64) each run ONE fuse+schedule+permute warp task (warp 0).
// One-warp-per-block keeps each greedy chain latency-bound on its own SM.
// ---------------------------------------------------------------------------
__global__ __launch_bounds__(H) void ntab_and_sched(const float* __restrict__ emb_table)
{
    if (blockIdx.x < VV) {
        // ---- N_table[v] = n-branch(sigmoid(emb_table[v])) ----
        __shared__ float b0[H], b1[H];
        int v = blockIdx.x, tid = threadIdx.x;
        float e = emb_table[v * H + tid];            // E == H == 1024
        b0[tid] = 1.0f / (1.0f + expf(-e));
        __syncthreads();
        float* src = b0; float* dst = b1;
#pragma unroll
        for (int l = 0; l < LL; l++) {
            float4  c  = g_cn[l * H + tid];
            unsigned pi = g_in[l * H + tid];
            float a = src[pi & 0xFFFFu], b = src[pi >> 16];
            dst[tid] = fmaf(c.w, a * b, fmaf(c.z, b, fmaf(c.y, a, c.x)));
            __syncthreads();
            float* t = src; src = dst; dst = t;
        }
        g_ntab[v * H + tid] = src[tid];
        return;
    }

    // ---- fuse + greedy bank schedule + coefficient permutation ----
    if (threadIdx.x >= 32) return;
    const unsigned FULL = 0xFFFFFFFFu;
    const int task = blockIdx.x - VV;          // 0..63
    const int sl = task >> 5, w = task & 31;
    const int lane = threadIdx.x;
    const int o = w * 32 + lane;               // gate within layer
    const int gate = sl * H + o;
    const int dom = (sl == 0) ? 2048 : 1024;   // copy1 base offset
    const int cj  = lane & 7;                  // candidate id: s=cj>>1, cp=cj&1
    const int csl = cj >> 1, ccp = cj & 1;

    // fuse k-layer pair for this gate
    float4   e  = g_ck[(2 * sl + 1) * H + o];
    unsigned pq = g_ik[(2 * sl + 1) * H + o];
    int p = pq & 0xFFFFu, q = pq >> 16;
    float4   A  = g_ck[2 * sl * H + p];
    float4   Bv = g_ck[2 * sl * H + q];
    unsigned ia = g_ik[2 * sl * H + p];        // leaves 0,1 (packed)
    unsigned ib = g_ik[2 * sl * H + q];        // leaves 2,3 (packed)

    float al[4] = {A.x, A.y, A.z, A.w};
    float be[4] = {Bv.x, Bv.y, Bv.z, Bv.w};
    float raw[16];
#pragma unroll
    for (int m2 = 0; m2 < 4; m2++)
#pragma unroll
        for (int m1 = 0; m1 < 4; m1++) {
            float cv = e.w * al[m1] * be[m2];
            if (m2 == 0) cv += e.y * al[m1];
            if (m1 == 0) cv += e.z * be[m2];
            if (m1 == 0 && m2 == 0) cv += e.x;
            raw[m1 | (m2 << 2)] = cv;
        }

    // greedy insertion (Round-12 decision-identical)
    unsigned cnt = 0;      // 4 x 8-bit per-slot counts; bank = lane
    unsigned myAsg = 0;    // per leaf t (byte t): bank<<3 | cp<<2 | slot

    for (int l = 0; l < 32; l++) {
        unsigned rx = __shfl_sync(FULL, ia, l);
        unsigned ry = __shfl_sync(FULL, ib, l);
        int lidx[4] = { (int)(rx & 0xFFFFu), (int)(rx >> 16),
                        (int)(ry & 0xFFFFu), (int)(ry >> 16) };
        unsigned used = 0, asg = 0;
#pragma unroll
        for (int t = 0; t < 4; t++) {
            int id0 = lidx[t];
            int A1 = dom + id0 + (id0 >> 5);
            int myA = ccp ? A1 : id0;
            unsigned cpk = __shfl_sync(FULL, cnt, myA & 31);
            unsigned c = (cpk >> (8 * csl)) & 0xFFu;
            if ((used >> csl) & 1u) c = 0x7FFu;
            unsigned key = (c << 3) | (unsigned)cj;
            unsigned kmin = __reduce_min_sync(FULL, key);
            int wj = (int)(kmin & 7u), ws = wj >> 1, wcp = wj & 1;
            int wb = (wcp ? A1 : id0) & 31;
            used |= 1u << ws;
            asg |= ((unsigned)((wb << 3) | (wcp << 2) | ws)) << (8 * t);
            if (lane == wb) cnt += 1u << (8 * ws);
        }
        if (lane == l) myAsg = asg;
    }

    // emit addresses + perm; permute coeffs into slot basis
    int idx[4] = { (int)(ia & 0xFFFFu), (int)(ia >> 16),
                   (int)(ib & 0xFFFFu), (int)(ib >> 16) };
    int aS[4];
    unsigned perm = 0;
#pragma unroll
    for (int t = 0; t < 4; t++) {
        unsigned f = (myAsg >> (8 * t)) & 0xFFu;
        int s = f & 3, cp = (f >> 2) & 1;
        aS[s] = cp ? (dom + idx[t] + (idx[t] >> 5)) : idx[t];
        perm |= (unsigned)t << (2 * s);
    }
    g_fka[gate] = make_uint2((unsigned)aS[0] | ((unsigned)aS[1] << 16),
                             (unsigned)aS[2] | ((unsigned)aS[3] << 16));

    float outc[16];
#pragma unroll
    for (int m = 0; m < 16; m++) {
        int om = 0;
#pragma unroll
        for (int s = 0; s < 4; s++)
            if ((m >> s) & 1) om |= 1 << ((perm >> (2 * s)) & 3);
        outc[m] = raw[om];
    }
    float4* op = &g_fkc[gate * 4];
#pragma unroll
    for (int j = 0; j < 4; j++)
        op[j] = make_float4(outc[4*j+0], outc[4*j+1], outc[4*j+2], outc[4*j+3]);
}

// ---------------------------------------------------------------------------
// Multilinear super-gate eval
// ---------------------------------------------------------------------------
__device__ __forceinline__ float eval16(const float4* c, uint2 ad, const float* base)
{
    float v0 = base[ad.x & 0xFFFFu], v1 = base[ad.x >> 16];
    float v2 = base[ad.y & 0xFFFFu], v3 = base[ad.y >> 16];
    float p01 = v0 * v1, p23 = v2 * v3;
    float r0 = fmaf(c[0].w, p01, fmaf(c[0].z, v1, fmaf(c[0].y, v0, c[0].x)));
    float r1 = fmaf(c[1].w, p01, fmaf(c[1].z, v1, fmaf(c[1].y, v0, c[1].x)));
    float r2 = fmaf(c[2].w, p01, fmaf(c[2].z, v1, fmaf(c[2].y, v0, c[2].x)));
    float r3 = fmaf(c[3].w, p01, fmaf(c[3].z, v1, fmaf(c[3].y, v0, c[3].x)));
    return fmaf(p23, r3, fmaf(v3, r2, fmaf(v2, r1, r0)));
}

// ---------------------------------------------------------------------------
// Kernel C: per-row recurrence (one CTA per batch row) + m-block + logit
// (Round-10/12 structure; tokens pre-scaled by H so the per-step n-row
//  address is a single add off a per-thread base pointer)
// ---------------------------------------------------------------------------
__global__ __launch_bounds__(H, 1) void recur_kernel(
    const int* __restrict__ x, const int* __restrict__ last_index,
    const float* __restrict__ rec_w, const float* __restrict__ rec_b,
    float* __restrict__ out)
{
    __shared__ float comb_all[COMB_ALL_SZ];
    __shared__ float t_all[T_ALL_SZ];
    __shared__ int   tok[SS];       // holds token*H (pre-scaled)
    __shared__ float red[32];

    int b = blockIdx.x, tid = threadIdx.x;

    float4 c0[4], c1[4];
#pragma unroll
    for (int j = 0; j < 4; j++) { c0[j] = g_fkc[tid * 4 + j]; c1[j] = g_fkc[(H + tid) * 4 + j]; }
    uint2 a0 = g_fka[tid], a1 = g_fka[H + tid];

    const int sk = tid + (tid >> 5);            // skew offset for index tid
    const float* ntab_t = g_ntab + tid;         // per-thread n-table base

    comb_all[tid] = 0.f; comb_all[1024 + tid] = 0.f;
    if (tid < SS) tok[tid] = x[b * SS + tid] * H;   // pre-scale token by H
    int li = last_index[b];
    __syncthreads();

    if (li > 0) {
        float nf0 = ntab_t[tok[0]];
        comb_all[tid] = nf0;             comb_all[2048 + sk] = nf0;
        comb_all[1024 + tid] = 0.f;      comb_all[3104 + sk] = 0.f;
        __syncthreads();

        for (int t = 0; t < li - 1; t++) {
            float nf = ntab_t[tok[t + 1]];                // prefetch next n-row
            float u = eval16(c0, a0, comb_all);           // super-layer 1
            t_all[tid] = u;  t_all[1024 + sk] = u;
            __syncthreads();
            float v = eval16(c1, a1, t_all);              // super-layer 2
            comb_all[1024 + tid] = v;  comb_all[3104 + sk] = v;   // h_{t+1}
            comb_all[tid]        = nf; comb_all[2048 + sk] = nf;  // n_{t+1}
            __syncthreads();
        }
        // comb copy0 now holds [n_{li-1}, h_{li-1}]
    }
    // li == 0: comb copy0 stays all-zero -> init_out path (matches reference)

    // ---- m block (once per row, reads copy0 only) ----
    float* mA = t_all;            // [0,1024)
    float* mB = t_all + 1024;     // [1024,2048)
    {
        float4 c; unsigned pi; float a, bb;
        c = g_cm[tid];        pi = g_im[tid];
        a = comb_all[pi & 0xFFFFu]; bb = comb_all[pi >> 16];
        mA[tid] = fmaf(c.w, a * bb, fmaf(c.z, bb, fmaf(c.y, a, c.x)));
        __syncthreads();
        c = g_cm[H + tid];    pi = g_im[H + tid];
        a = mA[pi & 0xFFFFu];  bb = mA[pi >> 16];
        mB[tid] = fmaf(c.w, a * bb, fmaf(c.z, bb, fmaf(c.y, a, c.x)));
        __syncthreads();
        c = g_cm[2*H + tid];  pi = g_im[2*H + tid];
        a = mB[pi & 0xFFFFu];  bb = mB[pi >> 16];
        mA[tid] = fmaf(c.w, a * bb, fmaf(c.z, bb, fmaf(c.y, a, c.x)));
        __syncthreads();
        c = g_cm[3*H + tid];  pi = g_im[3*H + tid];
        a = mA[pi & 0xFFFFu];  bb = mA[pi >> 16];
        mB[tid] = fmaf(c.w, a * bb, fmaf(c.z, bb, fmaf(c.y, a, c.x)));
        __syncthreads();
    }

    // ---- final layer (2048 gates, 2 per thread) + GF-sum + dot(rec_w) ----
    float4   cA = g_cmf[2 * tid],     cB = g_cmf[2 * tid + 1];
    unsigned pA = g_imf[2 * tid],     pB = g_imf[2 * tid + 1];
    float aA = mB[pA & 0xFFFFu], bA = mB[pA >> 16];
    float vA = fmaf(cA.w, aA * bA, fmaf(cA.z, bA, fmaf(cA.y, aA, cA.x)));
    float aB = mB[pB & 0xFFFFu], bB = mB[pB >> 16];
    float vB = fmaf(cB.w, aB * bB, fmaf(cB.z, bB, fmaf(cB.y, aB, cB.x)));
    float acc = (vA + vB) * rec_w[tid];   // GF=2: both gates map to rec_w[tid]

#pragma unroll
    for (int o = 16; o > 0; o >>= 1) acc += __shfl_xor_sync(0xFFFFFFFFu, acc, o);
    int warp = tid >> 5, lane = tid & 31;
    if (lane == 0) red[warp] = acc;
    __syncthreads();
    if (tid < 32) {
        float r = red[tid];
#pragma unroll
        for (int o = 16; o > 0; o >>= 1) r += __shfl_xor_sync(0xFFFFFFFFu, r, o);
        if (tid == 0) out[b] = r + rec_b[0];
    }
}

// ---------------------------------------------------------------------------
// kernel_launch
// ---------------------------------------------------------------------------
extern "C" void kernel_launch(void* const* d_in, const int* in_sizes, int n_in,
                              void* d_out, int out_size)
{
    const int*   x          = (const int*)  d_in[0];
    const int*   last_index = (const int*)  d_in[1];
    // d_in[2] = positive_mask (unused by the reference output)
    const float* emb_table  = (const float*)d_in[3];
    const float* n_w        = (const float*)d_in[4];
    const float* k_w        = (const float*)d_in[5];
    const float* m_w        = (const float*)d_in[6];
    const float* mf_w       = (const float*)d_in[7];
    const float* rec_w      = (const float*)d_in[8];
    const float* rec_b      = (const float*)d_in[9];
    const int*   n_idx      = (const int*)  d_in[10];
    const int*   k_idx0     = (const int*)  d_in[11];
    const int*   k_idx_rest = (const int*)  d_in[12];
    const int*   m_idx0     = (const int*)  d_in[13];
    const int*   m_idx_rest = (const int*)  d_in[14];
    const int*   m_idx_fin  = (const int*)  d_in[15];

    const int NG = 3 * LL * H + 2 * H;   // 14336
    precompute_coef<<<(NG + 255) / 256, 256>>>(
        n_w, k_w, m_w, mf_w, n_idx, k_idx0, k_idx_rest, m_idx0, m_idx_rest, m_idx_fin);
    ntab_and_sched<<<VV + 64, H>>>(emb_table);
    recur_kernel<<<BB, H>>>(x, last_index, rec_w, rec_b, (float*)d_out);
}

// round 17
// speedup vs baseline: 1.0081x; 1.0081x over previous
#include <cuda_runtime.h>
#include <cstdint>

// Problem constants (fixed by the dataset)
#define H   1024
#define LL  4
#define BB  128
#define SS  512
#define VV  128

// Dual-copy shared layouts in recur_kernel (Round-10/12 winner):
//  comb_all: [0,2048) copy0 = [n | h]; [2048, 2048+2112) copy1 skewed (addr = 2048 + i + (i>>5))
//  t_all:    [0,1024) copy0;           [1024, 1024+1056) copy1 skewed (addr = 1024 + i + (i>>5))
#define COMB_ALL_SZ 4160
#define T_ALL_SZ    2080

// ---------------------------------------------------------------------------
// Scratch (device globals — no allocation allowed in kernel_launch)
// ---------------------------------------------------------------------------
__device__ float4   g_cn [LL*H];
__device__ float4   g_ck [LL*H];
__device__ float4   g_cm [LL*H];
__device__ float4   g_cmf[2*H];
__device__ unsigned g_in [LL*H];
__device__ unsigned g_ik [LL*H];
__device__ unsigned g_im [LL*H];
__device__ unsigned g_imf[2*H];
__device__ float    g_ntab[VV*H];      // n-branch output per token

// Fused k super-layers (written by the scheduler)
__device__ float4   g_fkc[2*H*4];      // slot-permuted multilinear coeffs
__device__ uint2    g_fka[2*H];        // physical smem addresses (4 x 16-bit)

// ---------------------------------------------------------------------------
// Kernel A: softmax(w) -> affine gate coefficients, pack gather indices.
// Gate basis: out = c0 + c1*a + c2*b + c3*a*b
// Weight rows loaded as 4 x LDG128 (16-float rows are 64B aligned).
// ---------------------------------------------------------------------------
__global__ void precompute_coef(
    const float* __restrict__ n_w, const float* __restrict__ k_w,
    const float* __restrict__ m_w, const float* __restrict__ mf_w,
    const int* __restrict__ n_idx, const int* __restrict__ k_idx0,
    const int* __restrict__ k_idx_rest, const int* __restrict__ m_idx0,
    const int* __restrict__ m_idx_rest, const int* __restrict__ m_idx_fin)
{
    int g = blockIdx.x * blockDim.x + threadIdx.x;
    const int NG = 3 * LL * H + 2 * H;   // 14336
    if (g >= NG) return;

    const float* w; int i0, i1; float4* cdst; unsigned* idst; int slot;
    if (g < LL * H) {
        int l = g >> 10, o = g & (H - 1);
        w = n_w + (l * H + o) * 16;
        i0 = n_idx[(l * 2 + 0) * H + o];
        i1 = n_idx[(l * 2 + 1) * H + o];
        cdst = g_cn; idst = g_in; slot = g;
    } else if (g < 2 * LL * H) {
        int gg = g - LL * H, l = gg >> 10, o = gg & (H - 1);
        w = k_w + (l * H + o) * 16;
        if (l == 0) { i0 = k_idx0[o]; i1 = k_idx0[H + o]; }
        else        { i0 = k_idx_rest[((l - 1) * 2 + 0) * H + o];
                      i1 = k_idx_rest[((l - 1) * 2 + 1) * H + o]; }
        cdst = g_ck; idst = g_ik; slot = gg;
    } else if (g < 3 * LL * H) {
        int gg = g - 2 * LL * H, l = gg >> 10, o = gg & (H - 1);
        w = m_w + (l * H + o) * 16;
        if (l == 0) { i0 = m_idx0[o]; i1 = m_idx0[H + o]; }
        else        { i0 = m_idx_rest[((l - 1) * 2 + 0) * H + o];
                      i1 = m_idx_rest[((l - 1) * 2 + 1) * H + o]; }
        cdst = g_cm; idst = g_im; slot = gg;
    } else {
        int j = g - 3 * LL * H;               // 0..2047
        w = mf_w + j * 16;
        i0 = m_idx_fin[j]; i1 = m_idx_fin[2 * H + j];
        cdst = g_cmf; idst = g_imf; slot = j;
    }

    const float4* w4 = reinterpret_cast<const float4*>(w);
    float4 wa = w4[0], wb = w4[1], wc = w4[2], wd = w4[3];
    float p[16] = { wa.x, wa.y, wa.z, wa.w,  wb.x, wb.y, wb.z, wb.w,
                    wc.x, wc.y, wc.z, wc.w,  wd.x, wd.y, wd.z, wd.w };

    float mx = p[0];
#pragma unroll
    for (int i = 1; i < 16; i++) mx = fmaxf(mx, p[i]);
    float s = 0.f;
#pragma unroll
    for (int i = 0; i < 16; i++) { p[i] = expf(p[i] - mx); s += p[i]; }
    float inv = 1.0f / s;
#pragma unroll
    for (int i = 0; i < 16; i++) p[i] *= inv;

    float c0 = p[8] + p[9] + p[10] + p[11] + p[12] + p[13] + p[14] + p[15];
    float c1 = p[2] + p[3] + p[6] + p[7] - p[8] - p[9] - p[12] - p[13];
    float c2 = p[4] + p[5] + p[6] + p[7] - p[8] - p[9] - p[10] - p[11];
    float c3 = p[1] - p[2] - p[4] - 2.f * p[6] - p[7]
             + p[8] + 2.f * p[9] + p[11] + p[13] - p[14];

    cdst[slot] = make_float4(c0, c1, c2, c3);
    idst[slot] = (unsigned)i0 | ((unsigned)i1 << 16);
}

// ---------------------------------------------------------------------------
// Kernel B+S merged (Round-12 exact): blocks [0,VV) compute N_table rows;
// blocks [VV,VV+64) each run ONE fuse+schedule+permute warp task (warp 0).
// One-warp-per-block keeps each greedy chain latency-bound on its own SM.
// ---------------------------------------------------------------------------
__global__ __launch_bounds__(H) void ntab_and_sched(const float* __restrict__ emb_table)
{
    if (blockIdx.x < VV) {
        // ---- N_table[v] = n-branch(sigmoid(emb_table[v])) ----
        __shared__ float b0[H], b1[H];
        int v = blockIdx.x, tid = threadIdx.x;
        float e = emb_table[v * H + tid];            // E == H == 1024
        b0[tid] = 1.0f / (1.0f + expf(-e));
        __syncthreads();
        float* src = b0; float* dst = b1;
#pragma unroll
        for (int l = 0; l < LL; l++) {
            float4  c  = g_cn[l * H + tid];
            unsigned pi = g_in[l * H + tid];
            float a = src[pi & 0xFFFFu], b = src[pi >> 16];
            dst[tid] = fmaf(c.w, a * b, fmaf(c.z, b, fmaf(c.y, a, c.x)));
            __syncthreads();
            float* t = src; src = dst; dst = t;
        }
        g_ntab[v * H + tid] = src[tid];
        return;
    }

    // ---- fuse + greedy bank schedule + coefficient permutation ----
    if (threadIdx.x >= 32) return;
    const unsigned FULL = 0xFFFFFFFFu;
    const int task = blockIdx.x - VV;          // 0..63
    const int sl = task >> 5, w = task & 31;
    const int lane = threadIdx.x;
    const int o = w * 32 + lane;               // gate within layer
    const int gate = sl * H + o;
    const int dom = (sl == 0) ? 2048 : 1024;   // copy1 base offset
    const int cj  = lane & 7;                  // candidate id: s=cj>>1, cp=cj&1
    const int csl = cj >> 1, ccp = cj & 1;

    // fuse k-layer pair for this gate
    float4   e  = g_ck[(2 * sl + 1) * H + o];
    unsigned pq = g_ik[(2 * sl + 1) * H + o];
    int p = pq & 0xFFFFu, q = pq >> 16;
    float4   A  = g_ck[2 * sl * H + p];
    float4   Bv = g_ck[2 * sl * H + q];
    unsigned ia = g_ik[2 * sl * H + p];        // leaves 0,1 (packed)
    unsigned ib = g_ik[2 * sl * H + q];        // leaves 2,3 (packed)

    float al[4] = {A.x, A.y, A.z, A.w};
    float be[4] = {Bv.x, Bv.y, Bv.z, Bv.w};
    float raw[16];
#pragma unroll
    for (int m2 = 0; m2 < 4; m2++)
#pragma unroll
        for (int m1 = 0; m1 < 4; m1++) {
            float cv = e.w * al[m1] * be[m2];
            if (m2 == 0) cv += e.y * al[m1];
            if (m1 == 0) cv += e.z * be[m2];
            if (m1 == 0 && m2 == 0) cv += e.x;
            raw[m1 | (m2 << 2)] = cv;
        }

    // greedy insertion (Round-12 decision-identical)
    unsigned cnt = 0;      // 4 x 8-bit per-slot counts; bank = lane
    unsigned myAsg = 0;    // per leaf t (byte t): bank<<3 | cp<<2 | slot

    for (int l = 0; l < 32; l++) {
        unsigned rx = __shfl_sync(FULL, ia, l);
        unsigned ry = __shfl_sync(FULL, ib, l);
        int lidx[4] = { (int)(rx & 0xFFFFu), (int)(rx >> 16),
                        (int)(ry & 0xFFFFu), (int)(ry >> 16) };
        unsigned used = 0, asg = 0;
#pragma unroll
        for (int t = 0; t < 4; t++) {
            int id0 = lidx[t];
            int A1 = dom + id0 + (id0 >> 5);
            int myA = ccp ? A1 : id0;
            unsigned cpk = __shfl_sync(FULL, cnt, myA & 31);
            unsigned c = (cpk >> (8 * csl)) & 0xFFu;
            if ((used >> csl) & 1u) c = 0x7FFu;
            unsigned key = (c << 3) | (unsigned)cj;
            unsigned kmin = __reduce_min_sync(FULL, key);
            int wj = (int)(kmin & 7u), ws = wj >> 1, wcp = wj & 1;
            int wb = (wcp ? A1 : id0) & 31;
            used |= 1u << ws;
            asg |= ((unsigned)((wb << 3) | (wcp << 2) | ws)) << (8 * t);
            if (lane == wb) cnt += 1u << (8 * ws);
        }
        if (lane == l) myAsg = asg;
    }

    // emit addresses + perm; permute coeffs into slot basis
    int idx[4] = { (int)(ia & 0xFFFFu), (int)(ia >> 16),
                   (int)(ib & 0xFFFFu), (int)(ib >> 16) };
    int aS[4];
    unsigned perm = 0;
#pragma unroll
    for (int t = 0; t < 4; t++) {
        unsigned f = (myAsg >> (8 * t)) & 0xFFu;
        int s = f & 3, cp = (f >> 2) & 1;
        aS[s] = cp ? (dom + idx[t] + (idx[t] >> 5)) : idx[t];
        perm |= (unsigned)t << (2 * s);
    }
    g_fka[gate] = make_uint2((unsigned)aS[0] | ((unsigned)aS[1] << 16),
                             (unsigned)aS[2] | ((unsigned)aS[3] << 16));

    float outc[16];
#pragma unroll
    for (int m = 0; m < 16; m++) {
        int om = 0;
#pragma unroll
        for (int s = 0; s < 4; s++)
            if ((m >> s) & 1) om |= 1 << ((perm >> (2 * s)) & 3);
        outc[m] = raw[om];
    }
    float4* op = &g_fkc[gate * 4];
#pragma unroll
    for (int j = 0; j < 4; j++)
        op[j] = make_float4(outc[4*j+0], outc[4*j+1], outc[4*j+2], outc[4*j+3]);
}

// ---------------------------------------------------------------------------
// Multilinear super-gate eval
// ---------------------------------------------------------------------------
__device__ __forceinline__ float eval16(const float4* c, uint2 ad, const float* base)
{
    float v0 = base[ad.x & 0xFFFFu], v1 = base[ad.x >> 16];
    float v2 = base[ad.y & 0xFFFFu], v3 = base[ad.y >> 16];
    float p01 = v0 * v1, p23 = v2 * v3;
    float r0 = fmaf(c[0].w, p01, fmaf(c[0].z, v1, fmaf(c[0].y, v0, c[0].x)));
    float r1 = fmaf(c[1].w, p01, fmaf(c[1].z, v1, fmaf(c[1].y, v0, c[1].x)));
    float r2 = fmaf(c[2].w, p01, fmaf(c[2].z, v1, fmaf(c[2].y, v0, c[2].x)));
    float r3 = fmaf(c[3].w, p01, fmaf(c[3].z, v1, fmaf(c[3].y, v0, c[3].x)));
    return fmaf(p23, r3, fmaf(v3, r2, fmaf(v2, r1, r0)));
}

// ---------------------------------------------------------------------------
// Kernel C: per-row recurrence (one CTA per batch row) + m-block + logit
// (Round-10/12 exact: 1024 threads, 1 gate/thread — the balanced config)
// ---------------------------------------------------------------------------
__global__ __launch_bounds__(H, 1) void recur_kernel(
    const int* __restrict__ x, const int* __restrict__ last_index,
    const float* __restrict__ rec_w, const float* __restrict__ rec_b,
    float* __restrict__ out)
{
    __shared__ float comb_all[COMB_ALL_SZ];
    __shared__ float t_all[T_ALL_SZ];
    __shared__ int   tok[SS];
    __shared__ float red[32];

    int b = blockIdx.x, tid = threadIdx.x;

    float4 c0[4], c1[4];
#pragma unroll
    for (int j = 0; j < 4; j++) { c0[j] = g_fkc[tid * 4 + j]; c1[j] = g_fkc[(H + tid) * 4 + j]; }
    uint2 a0 = g_fka[tid], a1 = g_fka[H + tid];

    const int sk = tid + (tid >> 5);   // skew offset for index tid

    comb_all[tid] = 0.f; comb_all[1024 + tid] = 0.f;
    if (tid < SS) tok[tid] = x[b * SS + tid];
    int li = last_index[b];
    __syncthreads();

    if (li > 0) {
        float nf0 = g_ntab[tok[0] * H + tid];
        comb_all[tid] = nf0;             comb_all[2048 + sk] = nf0;
        comb_all[1024 + tid] = 0.f;      comb_all[3104 + sk] = 0.f;
        __syncthreads();

        for (int t = 0; t < li - 1; t++) {
            float nf = g_ntab[tok[t + 1] * H + tid];      // prefetch next n-row
            float u = eval16(c0, a0, comb_all);           // super-layer 1
            t_all[tid] = u;  t_all[1024 + sk] = u;
            __syncthreads();
            float v = eval16(c1, a1, t_all);              // super-layer 2
            comb_all[1024 + tid] = v;  comb_all[3104 + sk] = v;   // h_{t+1}
            comb_all[tid]        = nf; comb_all[2048 + sk] = nf;  // n_{t+1}
            __syncthreads();
        }
        // comb copy0 now holds [n_{li-1}, h_{li-1}]
    }
    // li == 0: comb copy0 stays all-zero -> init_out path (matches reference)

    // ---- m block (once per row, reads copy0 only) ----
    float* mA = t_all;            // [0,1024)
    float* mB = t_all + 1024;     // [1024,2048)
    {
        float4 c; unsigned pi; float a, bb;
        c = g_cm[tid];        pi = g_im[tid];
        a = comb_all[pi & 0xFFFFu]; bb = comb_all[pi >> 16];
        mA[tid] = fmaf(c.w, a * bb, fmaf(c.z, bb, fmaf(c.y, a, c.x)));
        __syncthreads();
        c = g_cm[H + tid];    pi = g_im[H + tid];
        a = mA[pi & 0xFFFFu];  bb = mA[pi >> 16];
        mB[tid] = fmaf(c.w, a * bb, fmaf(c.z, bb, fmaf(c.y, a, c.x)));
        __syncthreads();
        c = g_cm[2*H + tid];  pi = g_im[2*H + tid];
        a = mB[pi & 0xFFFFu];  bb = mB[pi >> 16];
        mA[tid] = fmaf(c.w, a * bb, fmaf(c.z, bb, fmaf(c.y, a, c.x)));
        __syncthreads();
        c = g_cm[3*H + tid];  pi = g_im[3*H + tid];
        a = mA[pi & 0xFFFFu];  bb = mA[pi >> 16];
        mB[tid] = fmaf(c.w, a * bb, fmaf(c.z, bb, fmaf(c.y, a, c.x)));
        __syncthreads();
    }

    // ---- final layer (2048 gates, 2 per thread) + GF-sum + dot(rec_w) ----
    float4   cA = g_cmf[2 * tid],     cB = g_cmf[2 * tid + 1];
    unsigned pA = g_imf[2 * tid],     pB = g_imf[2 * tid + 1];
    float aA = mB[pA & 0xFFFFu], bA = mB[pA >> 16];
    float vA = fmaf(cA.w, aA * bA, fmaf(cA.z, bA, fmaf(cA.y, aA, cA.x)));
    float aB = mB[pB & 0xFFFFu], bB = mB[pB >> 16];
    float vB = fmaf(cB.w, aB * bB, fmaf(cB.z, bB, fmaf(cB.y, aB, cB.x)));
    float acc = (vA + vB) * rec_w[tid];   // GF=2: both gates map to rec_w[tid]

#pragma unroll
    for (int o = 16; o > 0; o >>= 1) acc += __shfl_xor_sync(0xFFFFFFFFu, acc, o);
    int warp = tid >> 5, lane = tid & 31;
    if (lane == 0) red[warp] = acc;
    __syncthreads();
    if (tid < 32) {
        float r = red[tid];
#pragma unroll
        for (int o = 16; o > 0; o >>= 1) r += __shfl_xor_sync(0xFFFFFFFFu, r, o);
        if (tid == 0) out[b] = r + rec_b[0];
    }
}

// ---------------------------------------------------------------------------
// kernel_launch
// ---------------------------------------------------------------------------
extern "C" void kernel_launch(void* const* d_in, const int* in_sizes, int n_in,
                              void* d_out, int out_size)
{
    const int*   x          = (const int*)  d_in[0];
    const int*   last_index = (const int*)  d_in[1];
    // d_in[2] = positive_mask (unused by the reference output)
    const float* emb_table  = (const float*)d_in[3];
    const float* n_w        = (const float*)d_in[4];
    const float* k_w        = (const float*)d_in[5];
    const float* m_w        = (const float*)d_in[6];
    const float* mf_w       = (const float*)d_in[7];
    const float* rec_w      = (const float*)d_in[8];
    const float* rec_b      = (const float*)d_in[9];
    const int*   n_idx      = (const int*)  d_in[10];
    const int*   k_idx0     = (const int*)  d_in[11];
    const int*   k_idx_rest = (const int*)  d_in[12];
    const int*   m_idx0     = (const int*)  d_in[13];
    const int*   m_idx_rest = (const int*)  d_in[14];
    const int*   m_idx_fin  = (const int*)  d_in[15];

    const int NG = 3 * LL * H + 2 * H;   // 14336
    precompute_coef<<<(NG + 255) / 256, 256>>>(
        n_w, k_w, m_w, mf_w, n_idx, k_idx0, k_idx_rest, m_idx0, m_idx_rest, m_idx_fin);
    ntab_and_sched<<<VV + 64, H>>>(emb_table);
    recur_kernel<<<BB, H>>>(x, last_index, rec_w, rec_b, (float*)d_out);
}